// round 1
// baseline (speedup 1.0000x reference)
#include <cuda_runtime.h>
#include <math.h>

#define BSZ 4
#define DIMC 256
#define LSEQ 4096
#define DIN 512
#define DST 16
#define DTR 16
#define NTOK (BSZ * LSEQ)   // 16384

// -------- scratch (device globals; no allocation) --------
__device__ float g_xn[NTOK * DIMC];       // 16.8 MB
__device__ float g_xz[NTOK * 2 * DIN];    // 67 MB (xi | z)
__device__ float g_u[NTOK * DIN];         // 33.5 MB
__device__ float g_dbl[NTOK * 48];        // dt|B|C
__device__ float g_delta[NTOK * DIN];     // 33.5 MB
__device__ float g_y[NTOK * DIN];         // 33.5 MB
__device__ float g_wdtT[DTR * DIN];       // transposed dt_proj_w

// ============================================================
// 1. flatten + pe + LayerNorm  -> g_xn (token-major [m][c])
// ============================================================
__global__ __launch_bounds__(256) void ln_kernel(
    const float* __restrict__ x, const float* __restrict__ pe,
    const float* __restrict__ nw, const float* __restrict__ nb)
{
    __shared__ float sx[DIMC][33];
    int b  = blockIdx.y;
    int l0 = blockIdx.x * 32;
    int tid = threadIdx.x;

    const float* xb = x + (size_t)b * DIMC * LSEQ;
    for (int idx = tid; idx < DIMC * 32; idx += 256) {
        int c = idx >> 5, li = idx & 31;
        sx[c][li] = xb[(size_t)c * LSEQ + l0 + li];
    }
    __syncthreads();

    int warp = tid >> 5, lane = tid & 31;
    for (int tok = warp; tok < 32; tok += 8) {
        int l = l0 + tok;
        float v[8];
        float s = 0.f;
        #pragma unroll
        for (int k = 0; k < 8; k++) {
            int c = lane + 32 * k;
            v[k] = sx[c][tok] + pe[(size_t)l * DIMC + c];
            s += v[k];
        }
        #pragma unroll
        for (int off = 16; off; off >>= 1) s += __shfl_xor_sync(~0u, s, off);
        float mu = s * (1.f / DIMC);
        float vs = 0.f;
        #pragma unroll
        for (int k = 0; k < 8; k++) { float d = v[k] - mu; vs += d * d; }
        #pragma unroll
        for (int off = 16; off; off >>= 1) vs += __shfl_xor_sync(~0u, vs, off);
        float inv = rsqrtf(vs * (1.f / DIMC) + 1e-5f);
        int m = b * LSEQ + l;
        #pragma unroll
        for (int k = 0; k < 8; k++) {
            int c = lane + 32 * k;
            g_xn[(size_t)m * DIMC + c] = (v[k] - mu) * inv * nw[c] + nb[c];
        }
    }
}

// ============================================================
// 2. generic fp32 tiled GEMM: C[M,N] = A[M,K] * W[N,K]^T
//    BM=128, BN=64, BK=16, 256 threads, thread tile 8x4
//    TRANS_OUT: write C as out[b][n][l] (b = m>>12, l = m&4095)
// ============================================================
template<int TRANS_OUT>
__global__ __launch_bounds__(256) void gemm_kernel(
    const float* __restrict__ A, const float* __restrict__ W,
    float* __restrict__ C, int M, int N, int K)
{
    __shared__ float As[16 * 132];
    __shared__ float Ws[16 * 68];
    int tid = threadIdx.x;
    int m0 = blockIdx.y * 128;
    int n0 = blockIdx.x * 64;
    int ty = tid >> 4;          // 0..15 (m dir, 8 rows each)
    int tx = tid & 15;          // 0..15 (n dir, 4 cols each)

    float acc[8][4];
    #pragma unroll
    for (int i = 0; i < 8; i++)
        #pragma unroll
        for (int j = 0; j < 4; j++) acc[i][j] = 0.f;

    int lk  = (tid & 3) * 4;    // k sub-offset 0/4/8/12
    int lr  = tid >> 2;         // row 0..63

    for (int k0 = 0; k0 < K; k0 += 16) {
        #pragma unroll
        for (int r = 0; r < 2; r++) {
            int m = lr + r * 64;
            float4 av = *reinterpret_cast<const float4*>(
                &A[(size_t)(m0 + m) * K + k0 + lk]);
            As[(lk + 0) * 132 + m] = av.x;
            As[(lk + 1) * 132 + m] = av.y;
            As[(lk + 2) * 132 + m] = av.z;
            As[(lk + 3) * 132 + m] = av.w;
        }
        {
            int n = lr;
            float4 wv = make_float4(0.f, 0.f, 0.f, 0.f);
            if (n0 + n < N)
                wv = *reinterpret_cast<const float4*>(
                    &W[(size_t)(n0 + n) * K + k0 + lk]);
            Ws[(lk + 0) * 68 + n] = wv.x;
            Ws[(lk + 1) * 68 + n] = wv.y;
            Ws[(lk + 2) * 68 + n] = wv.z;
            Ws[(lk + 3) * 68 + n] = wv.w;
        }
        __syncthreads();
        #pragma unroll
        for (int kk = 0; kk < 16; kk++) {
            float4 a0 = *reinterpret_cast<const float4*>(&As[kk * 132 + ty * 8]);
            float4 a1 = *reinterpret_cast<const float4*>(&As[kk * 132 + ty * 8 + 4]);
            float4 wv = *reinterpret_cast<const float4*>(&Ws[kk * 68 + tx * 4]);
            float a[8] = {a0.x, a0.y, a0.z, a0.w, a1.x, a1.y, a1.z, a1.w};
            float w[4] = {wv.x, wv.y, wv.z, wv.w};
            #pragma unroll
            for (int i = 0; i < 8; i++)
                #pragma unroll
                for (int j = 0; j < 4; j++)
                    acc[i][j] = fmaf(a[i], w[j], acc[i][j]);
        }
        __syncthreads();
    }

    #pragma unroll
    for (int i = 0; i < 8; i++) {
        int m = m0 + ty * 8 + i;
        #pragma unroll
        for (int j = 0; j < 4; j++) {
            int n = n0 + tx * 4 + j;
            if (n < N) {
                if (TRANS_OUT) {
                    int b = m >> 12, l = m & 4095;
                    C[((size_t)b * N + n) * LSEQ + l] = acc[i][j];
                } else {
                    C[(size_t)m * N + n] = acc[i][j];
                }
            }
        }
    }
}

// ============================================================
// 3. causal conv1d(k=4) + bias + SiLU  -> g_u
// ============================================================
__global__ __launch_bounds__(256) void conv_kernel(
    const float* __restrict__ cw, const float* __restrict__ cb)
{
    int idx = blockIdx.x * 256 + threadIdx.x;   // over NTOK*DIN
    if (idx >= NTOK * DIN) return;
    int e = idx & 511;
    int m = idx >> 9;          // b*L + l
    int l = m & 4095;
    float acc = cb[e];
    #pragma unroll
    for (int j = 0; j < 4; j++) {
        int ls = l - 3 + j;
        if (ls >= 0)
            acc = fmaf(g_xz[(size_t)(m - 3 + j) * 1024 + e], cw[e * 4 + j], acc);
    }
    g_u[idx] = acc / (1.f + __expf(-acc));   // silu
}

// ============================================================
// 4a. transpose dt_proj_w  (512,16) -> (16,512)
// ============================================================
__global__ void wdt_transpose_kernel(const float* __restrict__ dtw)
{
    int idx = blockIdx.x * 256 + threadIdx.x;
    if (idx < DIN * DTR) {
        int d = idx >> 4, r = idx & 15;
        g_wdtT[r * DIN + d] = dtw[d * DTR + r];
    }
}

// 4b. delta = softplus(dt @ WdtT + bias)
__global__ __launch_bounds__(512) void dt_kernel(const float* __restrict__ dtb)
{
    __shared__ float sdt[16];
    int m = blockIdx.x;
    int d = threadIdx.x;
    if (d < 16) sdt[d] = g_dbl[(size_t)m * 48 + d];
    __syncthreads();
    float acc = dtb[d];
    #pragma unroll
    for (int r = 0; r < 16; r++)
        acc = fmaf(sdt[r], g_wdtT[r * DIN + d], acc);
    float sp = (acc > 20.f) ? acc : log1pf(__expf(acc));
    g_delta[(size_t)m * DIN + d] = sp;
}

// ============================================================
// 5. selective scan + u*D + silu(z) gating  -> g_y
//    warp = 2 channels (16 lanes each, lane = state index)
// ============================================================
__global__ __launch_bounds__(256) void scan_kernel(
    const float* __restrict__ A_log, const float* __restrict__ Dp)
{
    int b    = blockIdx.x >> 5;     // /32
    int dgrp = blockIdx.x & 31;     // 16 channels per block
    int warp = threadIdx.x >> 5;
    int lane = threadIdx.x & 31;
    int half = lane >> 4;
    int n    = lane & 15;
    int d    = dgrp * 16 + warp * 2 + half;

    float An = -__expf(A_log[d * DST + n]);
    float Dv = Dp[d];
    float h  = 0.f;

    const float* dl = g_delta + (size_t)b * LSEQ * DIN + d;
    const float* uu = g_u     + (size_t)b * LSEQ * DIN + d;
    const float* bc = g_dbl   + (size_t)b * LSEQ * 48;
    const float* zz = g_xz    + (size_t)b * LSEQ * 1024 + DIN + d;
    float*       yy = g_y     + (size_t)b * LSEQ * DIN + d;

    #pragma unroll 4
    for (int t = 0; t < LSEQ; t++) {
        float de = dl[(size_t)t * DIN];
        float ut = uu[(size_t)t * DIN];
        float Bn = bc[t * 48 + 16 + n];
        float Cn = bc[t * 48 + 32 + n];
        float dA = __expf(de * An);
        h = fmaf(dA, h, de * ut * Bn);
        float p = h * Cn;
        p += __shfl_xor_sync(~0u, p, 8, 16);
        p += __shfl_xor_sync(~0u, p, 4, 16);
        p += __shfl_xor_sync(~0u, p, 2, 16);
        p += __shfl_xor_sync(~0u, p, 1, 16);
        if (n == 0) {
            float zt = zz[(size_t)t * 1024];
            float yv = p + ut * Dv;
            yv *= zt / (1.f + __expf(-zt));
            yy[(size_t)t * DIN] = yv;
        }
    }
}

// ============================================================
// launch
// ============================================================
extern "C" void kernel_launch(void* const* d_in, const int* in_sizes, int n_in,
                              void* d_out, int out_size)
{
    const float* x        = (const float*)d_in[0];
    const float* pe       = (const float*)d_in[1];
    // d_in[2] = order (identity, unused)
    const float* norm_w   = (const float*)d_in[3];
    const float* norm_b   = (const float*)d_in[4];
    const float* in_proj  = (const float*)d_in[5];
    const float* conv_w   = (const float*)d_in[6];
    const float* conv_b   = (const float*)d_in[7];
    const float* x_proj   = (const float*)d_in[8];
    const float* dt_proj  = (const float*)d_in[9];
    const float* dt_b     = (const float*)d_in[10];
    const float* A_log    = (const float*)d_in[11];
    const float* Dp       = (const float*)d_in[12];
    const float* out_proj = (const float*)d_in[13];
    float* out = (float*)d_out;

    float* xn    = nullptr; cudaGetSymbolAddress((void**)&xn,    g_xn);
    float* xz    = nullptr; cudaGetSymbolAddress((void**)&xz,    g_xz);
    float* u     = nullptr; cudaGetSymbolAddress((void**)&u,     g_u);
    float* dbl   = nullptr; cudaGetSymbolAddress((void**)&dbl,   g_dbl);
    float* y     = nullptr; cudaGetSymbolAddress((void**)&y,     g_y);

    // 1. pe + layernorm
    ln_kernel<<<dim3(LSEQ / 32, BSZ), 256>>>(x, pe, norm_w, norm_b);

    // 2. in_proj: xz[16384,1024] = xn[16384,256] @ W^T
    gemm_kernel<0><<<dim3(1024 / 64, NTOK / 128), 256>>>(
        xn, in_proj, xz, NTOK, 2 * DIN, DIMC);

    // 3. conv + silu
    conv_kernel<<<(NTOK * DIN) / 256, 256>>>(conv_w, conv_b);

    // 4. x_proj: dbl[16384,48] = u @ W^T
    gemm_kernel<0><<<dim3(1, NTOK / 128), 256>>>(
        u, x_proj, dbl, NTOK, DTR + 2 * DST, DIN);

    // 5. dt_proj + softplus
    wdt_transpose_kernel<<<(DIN * DTR + 255) / 256, 256>>>(dt_proj);
    dt_kernel<<<NTOK, 512>>>(dt_b);

    // 6. selective scan + gating
    scan_kernel<<<BSZ * 32, 256>>>(A_log, Dp);

    // 7. out_proj with transposed store -> out[b][c][h][w]
    gemm_kernel<1><<<dim3(DIMC / 64, NTOK / 128), 256>>>(
        y, out_proj, out, NTOK, DIMC, DIN);
}

// round 2
// speedup vs baseline: 7.4721x; 7.4721x over previous
#include <cuda_runtime.h>
#include <math.h>

#define BSZ 4
#define DIMC 256
#define LSEQ 4096
#define DIN 512
#define DST 16
#define DTR 16
#define NTOK (BSZ * LSEQ)   // 16384
#define TC 128              // scan chunk length
#define NCH (LSEQ / TC)     // 32 chunks

// -------- scratch (device globals; no allocation) --------
__device__ float g_xn[NTOK * DIMC];
__device__ float g_xz[NTOK * 2 * DIN];    // xi | z
__device__ float g_u[NTOK * DIN];
__device__ float g_dbl[NTOK * 48];        // dt|B|C
__device__ float g_delta[NTOK * DIN];
__device__ float g_y[NTOK * DIN];
__device__ float g_wdtT[DTR * DIN];
__device__ float g_hE[BSZ * NCH * DIN * DST];   // chunk-end h
__device__ float g_aP[BSZ * NCH * DIN * DST];   // chunk prod(dA)
__device__ float g_h0[BSZ * NCH * DIN * DST];   // chunk start h

// ============================================================
// 1. flatten + pe + LayerNorm  -> g_xn (token-major [m][c])
// ============================================================
__global__ __launch_bounds__(256) void ln_kernel(
    const float* __restrict__ x, const float* __restrict__ pe,
    const float* __restrict__ nw, const float* __restrict__ nb)
{
    __shared__ float sx[DIMC][33];
    int b  = blockIdx.y;
    int l0 = blockIdx.x * 32;
    int tid = threadIdx.x;

    const float* xb = x + (size_t)b * DIMC * LSEQ;
    for (int idx = tid; idx < DIMC * 32; idx += 256) {
        int c = idx >> 5, li = idx & 31;
        sx[c][li] = xb[(size_t)c * LSEQ + l0 + li];
    }
    __syncthreads();

    int warp = tid >> 5, lane = tid & 31;
    for (int tok = warp; tok < 32; tok += 8) {
        int l = l0 + tok;
        float v[8];
        float s = 0.f;
        #pragma unroll
        for (int k = 0; k < 8; k++) {
            int c = lane + 32 * k;
            v[k] = sx[c][tok] + pe[(size_t)l * DIMC + c];
            s += v[k];
        }
        #pragma unroll
        for (int off = 16; off; off >>= 1) s += __shfl_xor_sync(~0u, s, off);
        float mu = s * (1.f / DIMC);
        float vs = 0.f;
        #pragma unroll
        for (int k = 0; k < 8; k++) { float d = v[k] - mu; vs += d * d; }
        #pragma unroll
        for (int off = 16; off; off >>= 1) vs += __shfl_xor_sync(~0u, vs, off);
        float inv = rsqrtf(vs * (1.f / DIMC) + 1e-5f);
        int m = b * LSEQ + l;
        #pragma unroll
        for (int k = 0; k < 8; k++) {
            int c = lane + 32 * k;
            g_xn[(size_t)m * DIMC + c] = (v[k] - mu) * inv * nw[c] + nb[c];
        }
    }
}

// ============================================================
// 2a. big GEMM: 128x128x16 tile, 256 threads, 8x8 microtile
//     C[M,N] = A[M,K] * W[N,K]^T ; requires M%128==0, N%128==0, K%16==0
//     TRANS: write out[b][n][l] (b=m>>12, l=m&4095)
// ============================================================
template<int TRANS>
__global__ __launch_bounds__(256, 2) void gemm128(
    const float* __restrict__ A, const float* __restrict__ W,
    float* __restrict__ C, int M, int N, int K)
{
    __shared__ float As[16 * 132];
    __shared__ float Ws[16 * 132];
    int tid = threadIdx.x;
    int m0 = blockIdx.y * 128;
    int n0 = blockIdx.x * 128;
    int ty = tid >> 4;          // 0..15
    int tx = tid & 15;          // 0..15
    int lk = (tid & 3) * 4;     // 0,4,8,12
    int lr = tid >> 2;          // 0..63

    const float* Ap = A + (size_t)(m0 + lr) * K + lk;
    const float* Wp = W + (size_t)(n0 + lr) * K + lk;

    float acc[8][8];
    #pragma unroll
    for (int i = 0; i < 8; i++)
        #pragma unroll
        for (int j = 0; j < 8; j++) acc[i][j] = 0.f;

    float4 a0 = *(const float4*)Ap;
    float4 a1 = *(const float4*)(Ap + (size_t)64 * K);
    float4 w0 = *(const float4*)Wp;
    float4 w1 = *(const float4*)(Wp + (size_t)64 * K);

    for (int k0 = 0; k0 < K; k0 += 16) {
        As[(lk + 0) * 132 + lr]      = a0.x;
        As[(lk + 1) * 132 + lr]      = a0.y;
        As[(lk + 2) * 132 + lr]      = a0.z;
        As[(lk + 3) * 132 + lr]      = a0.w;
        As[(lk + 0) * 132 + lr + 64] = a1.x;
        As[(lk + 1) * 132 + lr + 64] = a1.y;
        As[(lk + 2) * 132 + lr + 64] = a1.z;
        As[(lk + 3) * 132 + lr + 64] = a1.w;
        Ws[(lk + 0) * 132 + lr]      = w0.x;
        Ws[(lk + 1) * 132 + lr]      = w0.y;
        Ws[(lk + 2) * 132 + lr]      = w0.z;
        Ws[(lk + 3) * 132 + lr]      = w0.w;
        Ws[(lk + 0) * 132 + lr + 64] = w1.x;
        Ws[(lk + 1) * 132 + lr + 64] = w1.y;
        Ws[(lk + 2) * 132 + lr + 64] = w1.z;
        Ws[(lk + 3) * 132 + lr + 64] = w1.w;
        __syncthreads();

        if (k0 + 16 < K) {
            a0 = *(const float4*)(Ap + k0 + 16);
            a1 = *(const float4*)(Ap + (size_t)64 * K + k0 + 16);
            w0 = *(const float4*)(Wp + k0 + 16);
            w1 = *(const float4*)(Wp + (size_t)64 * K + k0 + 16);
        }

        #pragma unroll
        for (int kk = 0; kk < 16; kk++) {
            float4 x0 = *(const float4*)&As[kk * 132 + ty * 8];
            float4 x1 = *(const float4*)&As[kk * 132 + ty * 8 + 4];
            float4 y0 = *(const float4*)&Ws[kk * 132 + tx * 8];
            float4 y1 = *(const float4*)&Ws[kk * 132 + tx * 8 + 4];
            float av[8] = {x0.x, x0.y, x0.z, x0.w, x1.x, x1.y, x1.z, x1.w};
            float wv[8] = {y0.x, y0.y, y0.z, y0.w, y1.x, y1.y, y1.z, y1.w};
            #pragma unroll
            for (int i = 0; i < 8; i++)
                #pragma unroll
                for (int j = 0; j < 8; j++)
                    acc[i][j] = fmaf(av[i], wv[j], acc[i][j]);
        }
        __syncthreads();
    }

    if (!TRANS) {
        #pragma unroll
        for (int i = 0; i < 8; i++) {
            size_t row = (size_t)(m0 + ty * 8 + i) * N + n0 + tx * 8;
            float4 v0 = make_float4(acc[i][0], acc[i][1], acc[i][2], acc[i][3]);
            float4 v1 = make_float4(acc[i][4], acc[i][5], acc[i][6], acc[i][7]);
            *(float4*)&C[row]     = v0;
            *(float4*)&C[row + 4] = v1;
        }
    } else {
        int b = m0 >> 12;
        int l = (m0 & 4095) + ty * 8;
        #pragma unroll
        for (int j = 0; j < 8; j++) {
            int n = n0 + tx * 8 + j;
            float* cp = &C[((size_t)b * N + n) * LSEQ + l];
            float4 v0 = make_float4(acc[0][j], acc[1][j], acc[2][j], acc[3][j]);
            float4 v1 = make_float4(acc[4][j], acc[5][j], acc[6][j], acc[7][j]);
            *(float4*)cp       = v0;
            *(float4*)(cp + 4) = v1;
        }
    }
}

// ============================================================
// 2b. small-N GEMM (x_proj, N=48): 128x64x16 tile w/ guards
// ============================================================
__global__ __launch_bounds__(256) void gemm_small(
    const float* __restrict__ A, const float* __restrict__ W,
    float* __restrict__ C, int M, int N, int K)
{
    __shared__ float As[16 * 132];
    __shared__ float Ws[16 * 68];
    int tid = threadIdx.x;
    int m0 = blockIdx.y * 128;
    int n0 = blockIdx.x * 64;
    int ty = tid >> 4;
    int tx = tid & 15;

    float acc[8][4];
    #pragma unroll
    for (int i = 0; i < 8; i++)
        #pragma unroll
        for (int j = 0; j < 4; j++) acc[i][j] = 0.f;

    int lk = (tid & 3) * 4;
    int lr = tid >> 2;

    for (int k0 = 0; k0 < K; k0 += 16) {
        #pragma unroll
        for (int r = 0; r < 2; r++) {
            int m = lr + r * 64;
            float4 av = *reinterpret_cast<const float4*>(
                &A[(size_t)(m0 + m) * K + k0 + lk]);
            As[(lk + 0) * 132 + m] = av.x;
            As[(lk + 1) * 132 + m] = av.y;
            As[(lk + 2) * 132 + m] = av.z;
            As[(lk + 3) * 132 + m] = av.w;
        }
        {
            int n = lr;
            float4 wv = make_float4(0.f, 0.f, 0.f, 0.f);
            if (n0 + n < N)
                wv = *reinterpret_cast<const float4*>(
                    &W[(size_t)(n0 + n) * K + k0 + lk]);
            Ws[(lk + 0) * 68 + n] = wv.x;
            Ws[(lk + 1) * 68 + n] = wv.y;
            Ws[(lk + 2) * 68 + n] = wv.z;
            Ws[(lk + 3) * 68 + n] = wv.w;
        }
        __syncthreads();
        #pragma unroll
        for (int kk = 0; kk < 16; kk++) {
            float4 a0 = *reinterpret_cast<const float4*>(&As[kk * 132 + ty * 8]);
            float4 a1 = *reinterpret_cast<const float4*>(&As[kk * 132 + ty * 8 + 4]);
            float4 wv = *reinterpret_cast<const float4*>(&Ws[kk * 68 + tx * 4]);
            float a[8] = {a0.x, a0.y, a0.z, a0.w, a1.x, a1.y, a1.z, a1.w};
            float w[4] = {wv.x, wv.y, wv.z, wv.w};
            #pragma unroll
            for (int i = 0; i < 8; i++)
                #pragma unroll
                for (int j = 0; j < 4; j++)
                    acc[i][j] = fmaf(a[i], w[j], acc[i][j]);
        }
        __syncthreads();
    }

    #pragma unroll
    for (int i = 0; i < 8; i++) {
        int m = m0 + ty * 8 + i;
        #pragma unroll
        for (int j = 0; j < 4; j++) {
            int n = n0 + tx * 4 + j;
            if (n < N) C[(size_t)m * N + n] = acc[i][j];
        }
    }
}

// ============================================================
// 3. causal conv1d(k=4) + bias + SiLU  -> g_u
// ============================================================
__global__ __launch_bounds__(256) void conv_kernel(
    const float* __restrict__ cw, const float* __restrict__ cb)
{
    int idx = blockIdx.x * 256 + threadIdx.x;
    if (idx >= NTOK * DIN) return;
    int e = idx & 511;
    int m = idx >> 9;
    int l = m & 4095;
    float acc = cb[e];
    #pragma unroll
    for (int j = 0; j < 4; j++) {
        int ls = l - 3 + j;
        if (ls >= 0)
            acc = fmaf(g_xz[(size_t)(m - 3 + j) * 1024 + e], cw[e * 4 + j], acc);
    }
    g_u[idx] = acc / (1.f + __expf(-acc));
}

// ============================================================
// 4. dt_proj + softplus
// ============================================================
__global__ void wdt_transpose_kernel(const float* __restrict__ dtw)
{
    int idx = blockIdx.x * 256 + threadIdx.x;
    if (idx < DIN * DTR) {
        int d = idx >> 4, r = idx & 15;
        g_wdtT[r * DIN + d] = dtw[d * DTR + r];
    }
}

__global__ __launch_bounds__(512) void dt_kernel(const float* __restrict__ dtb)
{
    __shared__ float sdt[16];
    int m = blockIdx.x;
    int d = threadIdx.x;
    if (d < 16) sdt[d] = g_dbl[(size_t)m * 48 + d];
    __syncthreads();
    float acc = dtb[d];
    #pragma unroll
    for (int r = 0; r < 16; r++)
        acc = fmaf(sdt[r], g_wdtT[r * DIN + d], acc);
    float sp = (acc > 20.f) ? acc : log1pf(__expf(acc));
    g_delta[(size_t)m * DIN + d] = sp;
}

// ============================================================
// 5. chunked parallel selective scan
//    phase A (PHASE=0): per-chunk (prod dA, h_end)
//    phase C (PHASE=1): re-run chunk from h0, compute y+gating
//    block = (chunk, dgrp of 16 channels, batch), 8 warps x 2 ch
// ============================================================
template<int PHASE>
__global__ __launch_bounds__(256) void scan_phase(
    const float* __restrict__ A_log, const float* __restrict__ Dp)
{
    __shared__ float sD[TC * 16];
    __shared__ float sU[TC * 16];
    __shared__ float sB[TC * 16];
    __shared__ float sC[TC * 16];
    __shared__ float sZ[TC * 16];
    __shared__ float sY[TC * 16];

    int ch   = blockIdx.x;
    int dgrp = blockIdx.y;
    int b    = blockIdx.z;
    int tid  = threadIdx.x;
    int d0   = dgrp * 16;
    int m0   = b * LSEQ + ch * TC;

    for (int idx = tid; idx < TC * 16; idx += 256) {
        int t = idx >> 4, dd = idx & 15;
        size_t g = (size_t)(m0 + t) * DIN + d0 + dd;
        sD[idx] = g_delta[g];
        sU[idx] = g_u[g];
        if (PHASE) sZ[idx] = g_xz[(size_t)(m0 + t) * 1024 + DIN + d0 + dd];
    }
    for (int idx = tid; idx < TC * 32; idx += 256) {
        int t = idx >> 5, c = idx & 31;
        float v = g_dbl[(size_t)(m0 + t) * 48 + 16 + c];
        if (c < 16) sB[t * 16 + c] = v;
        else        sC[t * 16 + (c - 16)] = v;
    }
    __syncthreads();

    int warp = tid >> 5, lane = tid & 31;
    int half = lane >> 4, n = lane & 15;
    int dd = warp * 2 + half;
    int d  = d0 + dd;

    float An = -__expf(A_log[d * DST + n]);
    float h, aP = 1.f;
    if (PHASE) h = g_h0[(((size_t)b * NCH + ch) * DIN + d) * DST + n];
    else       h = 0.f;
    float Dv = PHASE ? Dp[d] : 0.f;

    #pragma unroll 4
    for (int t = 0; t < TC; t++) {
        float de = sD[t * 16 + dd];
        float ut = sU[t * 16 + dd];
        float Bn = sB[t * 16 + n];
        float dA = __expf(de * An);
        h = fmaf(dA, h, de * ut * Bn);
        if (PHASE) {
            float p = h * sC[t * 16 + n];
            p += __shfl_xor_sync(~0u, p, 8, 16);
            p += __shfl_xor_sync(~0u, p, 4, 16);
            p += __shfl_xor_sync(~0u, p, 2, 16);
            p += __shfl_xor_sync(~0u, p, 1, 16);
            if (n == 0) {
                float zt = sZ[t * 16 + dd];
                float yv = p + ut * Dv;
                yv *= zt / (1.f + __expf(-zt));
                sY[t * 16 + dd] = yv;
            }
        } else {
            aP *= dA;
        }
    }

    if (PHASE) {
        __syncthreads();
        for (int idx = tid; idx < TC * 16; idx += 256) {
            int t = idx >> 4, ddw = idx & 15;
            g_y[(size_t)(m0 + t) * DIN + d0 + ddw] = sY[idx];
        }
    } else {
        size_t o = (((size_t)b * NCH + ch) * DIN + d) * DST + n;
        g_hE[o] = h;
        g_aP[o] = aP;
    }
}

// phase B: serial combine across 32 chunk summaries
__global__ __launch_bounds__(256) void scan_combine()
{
    int idx = blockIdx.x * 256 + threadIdx.x;   // B*DIN*DST = 32768
    if (idx >= BSZ * DIN * DST) return;
    int b  = idx / (DIN * DST);
    int dn = idx % (DIN * DST);
    float h = 0.f;
    #pragma unroll 4
    for (int ch = 0; ch < NCH; ch++) {
        size_t o = ((size_t)b * NCH + ch) * (DIN * DST) + dn;
        g_h0[o] = h;
        h = fmaf(g_aP[o], h, g_hE[o]);
    }
}

// ============================================================
// launch
// ============================================================
extern "C" void kernel_launch(void* const* d_in, const int* in_sizes, int n_in,
                              void* d_out, int out_size)
{
    const float* x        = (const float*)d_in[0];
    const float* pe       = (const float*)d_in[1];
    const float* norm_w   = (const float*)d_in[3];
    const float* norm_b   = (const float*)d_in[4];
    const float* in_proj  = (const float*)d_in[5];
    const float* conv_w   = (const float*)d_in[6];
    const float* conv_b   = (const float*)d_in[7];
    const float* x_proj   = (const float*)d_in[8];
    const float* dt_proj  = (const float*)d_in[9];
    const float* dt_b     = (const float*)d_in[10];
    const float* A_log    = (const float*)d_in[11];
    const float* Dp       = (const float*)d_in[12];
    const float* out_proj = (const float*)d_in[13];
    float* out = (float*)d_out;

    float* xn  = nullptr; cudaGetSymbolAddress((void**)&xn,  g_xn);
    float* xz  = nullptr; cudaGetSymbolAddress((void**)&xz,  g_xz);
    float* u   = nullptr; cudaGetSymbolAddress((void**)&u,   g_u);
    float* dbl = nullptr; cudaGetSymbolAddress((void**)&dbl, g_dbl);
    float* y   = nullptr; cudaGetSymbolAddress((void**)&y,   g_y);

    // 1. pe + layernorm
    ln_kernel<<<dim3(LSEQ / 32, BSZ), 256>>>(x, pe, norm_w, norm_b);

    // 2. in_proj: xz[16384,1024] = xn[16384,256] @ W^T
    gemm128<0><<<dim3(1024 / 128, NTOK / 128), 256>>>(
        xn, in_proj, xz, NTOK, 2 * DIN, DIMC);

    // 3. conv + silu
    conv_kernel<<<(NTOK * DIN) / 256, 256>>>(conv_w, conv_b);

    // 4. x_proj: dbl[16384,48] = u @ W^T
    gemm_small<<<dim3(1, NTOK / 128), 256>>>(
        u, x_proj, dbl, NTOK, DTR + 2 * DST, DIN);

    // 5. dt_proj + softplus
    wdt_transpose_kernel<<<(DIN * DTR + 255) / 256, 256>>>(dt_proj);
    dt_kernel<<<NTOK, 512>>>(dt_b);

    // 6. chunked parallel scan
    scan_phase<0><<<dim3(NCH, 32, BSZ), 256>>>(A_log, Dp);
    scan_combine<<<(BSZ * DIN * DST) / 256, 256>>>();
    scan_phase<1><<<dim3(NCH, 32, BSZ), 256>>>(A_log, Dp);

    // 7. out_proj with transposed store -> out[b][c][h][w]
    gemm128<1><<<dim3(DIMC / 128, NTOK / 128), 256>>>(
        y, out_proj, out, NTOK, DIMC, DIN);
}

// round 4
// speedup vs baseline: 8.6205x; 1.1537x over previous
#include <cuda_runtime.h>
#include <math.h>
#include <stdint.h>

#define BSZ 4
#define DIMC 256
#define LSEQ 4096
#define DIN 512
#define DST 16
#define DTR 16
#define NTOK (BSZ * LSEQ)   // 16384
#define TC 128              // scan chunk length
#define NCH (LSEQ / TC)     // 32 chunks

// -------- scratch (device globals; no allocation) --------
__device__ float g_xn[NTOK * DIMC];
__device__ float g_xz[NTOK * 2 * DIN];    // xi | z
__device__ float g_u[NTOK * DIN];
__device__ float g_dbl[NTOK * 48];        // dt|B|C
__device__ float g_delta[NTOK * DIN];
__device__ float g_y[NTOK * DIN];
__device__ float g_wdtT[DTR * DIN];
__device__ float g_hE[BSZ * NCH * DIN * DST];
__device__ float g_aP[BSZ * NCH * DIN * DST];
__device__ float g_h0[BSZ * NCH * DIN * DST];

// ============================================================
// helpers
// ============================================================
__device__ __forceinline__ uint32_t smem_u32(const void* p) {
    uint32_t a;
    asm("{ .reg .u64 t; cvta.to.shared.u64 t, %1; cvt.u32.u64 %0, t; }"
        : "=r"(a) : "l"(p));
    return a;
}

__device__ __forceinline__ void cp16(uint32_t dst, const void* src, bool pred) {
    int sz = pred ? 16 : 0;
    asm volatile("cp.async.cg.shared.global [%0], [%1], 16, %2;"
                 :: "r"(dst), "l"(src), "r"(sz) : "memory");
}

__device__ __forceinline__ void spl(float v, uint32_t& h, uint32_t& l) {
    uint32_t u = __float_as_uint(v);
    h = u & 0xffffe000u;
    l = __float_as_uint(v - __uint_as_float(h));
}

__device__ __forceinline__ void mma8(float* d, const uint32_t* a,
                                     uint32_t b0, uint32_t b1) {
    asm volatile(
        "mma.sync.aligned.m16n8k8.row.col.f32.tf32.tf32.f32 "
        "{%0,%1,%2,%3}, {%4,%5,%6,%7}, {%8,%9}, {%0,%1,%2,%3};"
        : "+f"(d[0]), "+f"(d[1]), "+f"(d[2]), "+f"(d[3])
        : "r"(a[0]), "r"(a[1]), "r"(a[2]), "r"(a[3]), "r"(b0), "r"(b1));
}

// ============================================================
// split-tf32 mma GEMM: C[M,N] = A[M,K] * B[N,K]^T  (3xTF32)
//   CTA tile 128x128, BK=32, 8 warps (warp tile 32x64)
//   A rows full (M % 128 == 0); B rows guarded by bRows.
//   OUT_MODE 0: C[m*ldC + n] row-major
//   OUT_MODE 1: out[b][c][l]; m = channel c, n = global token (b,l)
// smem: double buffer x (A 128x36 + B 128x36) fp32 = 73728 B
// ============================================================
#define GPAD 36
#define GBUF (128 * GPAD)          // floats per matrix buffer
#define GSMEM_BYTES (2 * 2 * GBUF * 4)

template<int OUT_MODE>
__global__ __launch_bounds__(256, 2) void mmagemm(
    const float* __restrict__ Ag, const float* __restrict__ Bg,
    float* __restrict__ C, int K, int bRows, int ldC)
{
    extern __shared__ float s[];
    const uint32_t sbase = smem_u32(s);
    const int tid  = threadIdx.x;
    const int lane = tid & 31, wid = tid >> 5;
    const int gid  = lane >> 2, tig = lane & 3;
    const int wm   = wid & 3,  wn  = wid >> 2;

    const int m0 = blockIdx.y * 128;
    const int n0 = blockIdx.x * 128;
    const int NC = K >> 5;

    const int ldrow = tid >> 3;     // 0..31 ... wait: idx per i below
    (void)ldrow;

    float acc[2][8][4];
    #pragma unroll
    for (int i = 0; i < 2; i++)
        #pragma unroll
        for (int j = 0; j < 8; j++)
            #pragma unroll
            for (int k = 0; k < 4; k++) acc[i][j][k] = 0.f;

    // ---- async tile loader ----
    auto issue = [&](int ck) {
        const int buf = ck & 1;
        const uint32_t dA = sbase + (uint32_t)(buf * 2 * GBUF) * 4u;
        const uint32_t dB = dA + (uint32_t)GBUF * 4u;
        const int k0 = ck * 32;
        #pragma unroll
        for (int i = 0; i < 4; i++) {
            int idx = tid + (i << 8);       // 0..1023
            int row = idx >> 3;             // 0..127
            int q   = idx & 7;              // 16B chunk within 32 floats
            cp16(dA + (uint32_t)(row * GPAD + q * 4) * 4u,
                 Ag + (size_t)(m0 + row) * K + k0 + q * 4, true);
            bool p = (n0 + row) < bRows;
            const float* bs = Bg + (size_t)(p ? (n0 + row) : 0) * K + k0 + q * 4;
            cp16(dB + (uint32_t)(row * GPAD + q * 4) * 4u, bs, p);
        }
        asm volatile("cp.async.commit_group;" ::: "memory");
    };

    issue(0);

    for (int ck = 0; ck < NC; ck++) {
        if (ck + 1 < NC) {
            issue(ck + 1);
            asm volatile("cp.async.wait_group 1;" ::: "memory");
        } else {
            asm volatile("cp.async.wait_group 0;" ::: "memory");
        }
        __syncthreads();

        const float* As = s + (ck & 1) * 2 * GBUF;
        const float* Bs = As + GBUF;
        const float* Aw = As + (wm * 32) * GPAD;
        const float* Bw = Bs + (wn * 64) * GPAD;

        #pragma unroll
        for (int ks = 0; ks < 4; ks++) {
            const int kc = ks * 8 + tig;
            uint32_t ah[2][4], al[2][4];
            #pragma unroll
            for (int tm = 0; tm < 2; tm++) {
                const float* ap = Aw + (tm * 16 + gid) * GPAD;
                float r0 = ap[kc];
                float r1 = ap[8 * GPAD + kc];
                float r2 = ap[kc + 4];
                float r3 = ap[8 * GPAD + kc + 4];
                spl(r0, ah[tm][0], al[tm][0]);
                spl(r1, ah[tm][1], al[tm][1]);
                spl(r2, ah[tm][2], al[tm][2]);
                spl(r3, ah[tm][3], al[tm][3]);
            }
            #pragma unroll
            for (int tn = 0; tn < 8; tn++) {
                const float* bp = Bw + (tn * 8 + gid) * GPAD;
                float b0 = bp[kc];
                float b1 = bp[kc + 4];
                uint32_t bh0, bh1, bl0, bl1;
                spl(b0, bh0, bl0);
                spl(b1, bh1, bl1);
                #pragma unroll
                for (int tm = 0; tm < 2; tm++) {
                    mma8(acc[tm][tn], ah[tm], bh0, bh1);
                    mma8(acc[tm][tn], al[tm], bh0, bh1);
                    mma8(acc[tm][tn], ah[tm], bl0, bl1);
                }
            }
        }
        __syncthreads();
    }

    // ---- epilogue ----
    #pragma unroll
    for (int tm = 0; tm < 2; tm++) {
        int m = m0 + wm * 32 + tm * 16 + gid;
        #pragma unroll
        for (int tn = 0; tn < 8; tn++) {
            int n = n0 + wn * 64 + tn * 8 + tig * 2;
            if (OUT_MODE == 0) {
                if (n + 2 <= bRows) {
                    float2 v0 = make_float2(acc[tm][tn][0], acc[tm][tn][1]);
                    float2 v1 = make_float2(acc[tm][tn][2], acc[tm][tn][3]);
                    *(float2*)&C[(size_t)m * ldC + n] = v0;
                    *(float2*)&C[(size_t)(m + 8) * ldC + n] = v1;
                }
            } else {
                int bb = n >> 12;
                int l  = n & 4095;
                size_t base = ((size_t)bb * DIMC + m) * LSEQ + l;
                float2 v0 = make_float2(acc[tm][tn][0], acc[tm][tn][1]);
                float2 v1 = make_float2(acc[tm][tn][2], acc[tm][tn][3]);
                *(float2*)&C[base] = v0;
                *(float2*)&C[base + (size_t)8 * LSEQ] = v1;
            }
        }
    }
}

// ============================================================
// 1. flatten + pe + LayerNorm  -> g_xn (token-major [m][c])
// ============================================================
__global__ __launch_bounds__(256) void ln_kernel(
    const float* __restrict__ x, const float* __restrict__ pe,
    const float* __restrict__ nw, const float* __restrict__ nb)
{
    __shared__ float sx[DIMC][33];
    int b  = blockIdx.y;
    int l0 = blockIdx.x * 32;
    int tid = threadIdx.x;

    const float* xb = x + (size_t)b * DIMC * LSEQ;
    for (int idx = tid; idx < DIMC * 32; idx += 256) {
        int c = idx >> 5, li = idx & 31;
        sx[c][li] = xb[(size_t)c * LSEQ + l0 + li];
    }
    __syncthreads();

    int warp = tid >> 5, lane = tid & 31;
    for (int tok = warp; tok < 32; tok += 8) {
        int l = l0 + tok;
        float v[8];
        float s = 0.f;
        #pragma unroll
        for (int k = 0; k < 8; k++) {
            int c = lane + 32 * k;
            v[k] = sx[c][tok] + pe[(size_t)l * DIMC + c];
            s += v[k];
        }
        #pragma unroll
        for (int off = 16; off; off >>= 1) s += __shfl_xor_sync(~0u, s, off);
        float mu = s * (1.f / DIMC);
        float vs = 0.f;
        #pragma unroll
        for (int k = 0; k < 8; k++) { float d = v[k] - mu; vs += d * d; }
        #pragma unroll
        for (int off = 16; off; off >>= 1) vs += __shfl_xor_sync(~0u, vs, off);
        float inv = rsqrtf(vs * (1.f / DIMC) + 1e-5f);
        int m = b * LSEQ + l;
        #pragma unroll
        for (int k = 0; k < 8; k++) {
            int c = lane + 32 * k;
            g_xn[(size_t)m * DIMC + c] = (v[k] - mu) * inv * nw[c] + nb[c];
        }
    }
}

// ============================================================
// 3. causal conv1d(k=4) + bias + SiLU  -> g_u
// ============================================================
__global__ __launch_bounds__(256) void conv_kernel(
    const float* __restrict__ cw, const float* __restrict__ cb)
{
    int idx = blockIdx.x * 256 + threadIdx.x;
    if (idx >= NTOK * DIN) return;
    int e = idx & 511;
    int m = idx >> 9;
    int l = m & 4095;
    float acc = cb[e];
    #pragma unroll
    for (int j = 0; j < 4; j++) {
        int ls = l - 3 + j;
        if (ls >= 0)
            acc = fmaf(g_xz[(size_t)(m - 3 + j) * 1024 + e], cw[e * 4 + j], acc);
    }
    g_u[idx] = acc / (1.f + __expf(-acc));
}

// ============================================================
// 4. dt_proj + softplus
// ============================================================
__global__ void wdt_transpose_kernel(const float* __restrict__ dtw)
{
    int idx = blockIdx.x * 256 + threadIdx.x;
    if (idx < DIN * DTR) {
        int d = idx >> 4, r = idx & 15;
        g_wdtT[r * DIN + d] = dtw[d * DTR + r];
    }
}

__global__ __launch_bounds__(512) void dt_kernel(const float* __restrict__ dtb)
{
    __shared__ float sdt[16];
    int m = blockIdx.x;
    int d = threadIdx.x;
    if (d < 16) sdt[d] = g_dbl[(size_t)m * 48 + d];
    __syncthreads();
    float acc = dtb[d];
    #pragma unroll
    for (int r = 0; r < 16; r++)
        acc = fmaf(sdt[r], g_wdtT[r * DIN + d], acc);
    float sp = (acc > 20.f) ? acc : log1pf(__expf(acc));
    g_delta[(size_t)m * DIN + d] = sp;
}

// ============================================================
// 5. chunked parallel selective scan
// ============================================================
template<int PHASE>
__global__ __launch_bounds__(256) void scan_phase(
    const float* __restrict__ A_log, const float* __restrict__ Dp)
{
    __shared__ float sD[TC * 16];
    __shared__ float sU[TC * 16];
    __shared__ float sB[TC * 16];
    __shared__ float sC[TC * 16];
    __shared__ float sZ[TC * 16];
    __shared__ float sY[TC * 16];

    int ch   = blockIdx.x;
    int dgrp = blockIdx.y;
    int b    = blockIdx.z;
    int tid  = threadIdx.x;
    int d0   = dgrp * 16;
    int m0   = b * LSEQ + ch * TC;

    for (int idx = tid; idx < TC * 16; idx += 256) {
        int t = idx >> 4, dd = idx & 15;
        size_t g = (size_t)(m0 + t) * DIN + d0 + dd;
        sD[idx] = g_delta[g];
        sU[idx] = g_u[g];
        if (PHASE) sZ[idx] = g_xz[(size_t)(m0 + t) * 1024 + DIN + d0 + dd];
    }
    for (int idx = tid; idx < TC * 32; idx += 256) {
        int t = idx >> 5, c = idx & 31;
        float v = g_dbl[(size_t)(m0 + t) * 48 + 16 + c];
        if (c < 16) sB[t * 16 + c] = v;
        else        sC[t * 16 + (c - 16)] = v;
    }
    __syncthreads();

    int warp = tid >> 5, lane = tid & 31;
    int half = lane >> 4, n = lane & 15;
    int dd = warp * 2 + half;
    int d  = d0 + dd;

    float An = -__expf(A_log[d * DST + n]);
    float h, aP = 1.f;
    if (PHASE) h = g_h0[(((size_t)b * NCH + ch) * DIN + d) * DST + n];
    else       h = 0.f;
    float Dv = PHASE ? Dp[d] : 0.f;

    #pragma unroll 4
    for (int t = 0; t < TC; t++) {
        float de = sD[t * 16 + dd];
        float ut = sU[t * 16 + dd];
        float Bn = sB[t * 16 + n];
        float dA = __expf(de * An);
        h = fmaf(dA, h, de * ut * Bn);
        if (PHASE) {
            float p = h * sC[t * 16 + n];
            p += __shfl_xor_sync(~0u, p, 8, 16);
            p += __shfl_xor_sync(~0u, p, 4, 16);
            p += __shfl_xor_sync(~0u, p, 2, 16);
            p += __shfl_xor_sync(~0u, p, 1, 16);
            if (n == 0) {
                float zt = sZ[t * 16 + dd];
                float yv = p + ut * Dv;
                yv *= zt / (1.f + __expf(-zt));
                sY[t * 16 + dd] = yv;
            }
        } else {
            aP *= dA;
        }
    }

    if (PHASE) {
        __syncthreads();
        for (int idx = tid; idx < TC * 16; idx += 256) {
            int t = idx >> 4, ddw = idx & 15;
            g_y[(size_t)(m0 + t) * DIN + d0 + ddw] = sY[idx];
        }
    } else {
        size_t o = (((size_t)b * NCH + ch) * DIN + d) * DST + n;
        g_hE[o] = h;
        g_aP[o] = aP;
    }
}

__global__ __launch_bounds__(256) void scan_combine()
{
    int idx = blockIdx.x * 256 + threadIdx.x;
    if (idx >= BSZ * DIN * DST) return;
    int b  = idx / (DIN * DST);
    int dn = idx % (DIN * DST);
    float h = 0.f;
    #pragma unroll 4
    for (int ch = 0; ch < NCH; ch++) {
        size_t o = ((size_t)b * NCH + ch) * (DIN * DST) + dn;
        g_h0[o] = h;
        h = fmaf(g_aP[o], h, g_hE[o]);
    }
}

// ============================================================
// launch
// ============================================================
extern "C" void kernel_launch(void* const* d_in, const int* in_sizes, int n_in,
                              void* d_out, int out_size)
{
    const float* x        = (const float*)d_in[0];
    const float* pe       = (const float*)d_in[1];
    const float* norm_w   = (const float*)d_in[3];
    const float* norm_b   = (const float*)d_in[4];
    const float* in_proj  = (const float*)d_in[5];
    const float* conv_w   = (const float*)d_in[6];
    const float* conv_b   = (const float*)d_in[7];
    const float* x_proj   = (const float*)d_in[8];
    const float* dt_proj  = (const float*)d_in[9];
    const float* dt_b     = (const float*)d_in[10];
    const float* A_log    = (const float*)d_in[11];
    const float* Dp       = (const float*)d_in[12];
    const float* out_proj = (const float*)d_in[13];
    float* out = (float*)d_out;

    float* xn  = nullptr; cudaGetSymbolAddress((void**)&xn,  g_xn);
    float* xz  = nullptr; cudaGetSymbolAddress((void**)&xz,  g_xz);
    float* u   = nullptr; cudaGetSymbolAddress((void**)&u,   g_u);
    float* dbl = nullptr; cudaGetSymbolAddress((void**)&dbl, g_dbl);
    float* y   = nullptr; cudaGetSymbolAddress((void**)&y,   g_y);

    cudaFuncSetAttribute(mmagemm<0>,
        cudaFuncAttributeMaxDynamicSharedMemorySize, GSMEM_BYTES);
    cudaFuncSetAttribute(mmagemm<1>,
        cudaFuncAttributeMaxDynamicSharedMemorySize, GSMEM_BYTES);

    // 1. pe + layernorm
    ln_kernel<<<dim3(LSEQ / 32, BSZ), 256>>>(x, pe, norm_w, norm_b);

    // 2. in_proj: xz[16384,1024] = xn[16384,256] @ in_proj^T
    mmagemm<0><<<dim3(1024 / 128, NTOK / 128), 256, GSMEM_BYTES>>>(
        xn, in_proj, xz, DIMC, 2 * DIN, 2 * DIN);

    // 3. conv + silu
    conv_kernel<<<(NTOK * DIN) / 256, 256>>>(conv_w, conv_b);

    // 4. x_proj: dbl[16384,48] = u @ x_proj^T  (N=48 padded in-tile)
    mmagemm<0><<<dim3(1, NTOK / 128), 256, GSMEM_BYTES>>>(
        u, x_proj, dbl, DIN, 48, 48);

    // 5. dt_proj + softplus
    wdt_transpose_kernel<<<(DIN * DTR + 255) / 256, 256>>>(dt_proj);
    dt_kernel<<<NTOK, 512>>>(dt_b);

    // 6. chunked parallel scan
    scan_phase<0><<<dim3(NCH, 32, BSZ), 256>>>(A_log, Dp);
    scan_combine<<<(BSZ * DIN * DST) / 256, 256>>>();
    scan_phase<1><<<dim3(NCH, 32, BSZ), 256>>>(A_log, Dp);

    // 7. out_proj: A = out_proj_w (channels as M), B = g_y (tokens as N),
    //    transposed store lands contiguous along l
    mmagemm<1><<<dim3(NTOK / 128, DIMC / 128), 256, GSMEM_BYTES>>>(
        out_proj, y, out, DIN, NTOK, 0);
}